// round 6
// baseline (speedup 1.0000x reference)
#include <cuda_runtime.h>

// Fixed problem shapes
#define BB    4
#define CC    256
#define HH    128
#define WW    256
#define GG    4
#define CG    64             // channels per group
#define CH    32             // channels per smem half
#define WIN   9              // 1x9 window
#define PAD   4
#define RWLEN (WW + 2*PAD)   // 264 floats per padded channel row
#define PLANE (HH*WW)

// 3 blocks/SM: ~85-reg budget (~79 live in phase 2 incl. depth-2 prefetch),
// 3 x 33.8 KB smem = 101 KB, 24 warps/SM.
__global__ __launch_bounds__(256, 3)
void crestereo_corr_kernel(const float* __restrict__ left,
                           const float* __restrict__ right,
                           const float* __restrict__ flow,
                           float* __restrict__ out)
{
    extern __shared__ float s_rw[];   // [CH][RWLEN] = 32*264 floats = 33792 B

    const int tid = threadIdx.x;      // 0..255
    const int bg  = blockIdx.x;       // 0..15, (b,g) fastest -> same-h blocks coscheduled
    const int b   = bg >> 2;
    const int g   = bg & 3;
    const int h   = blockIdx.y;       // 0..127

    // -------- bilinear sampling parameters (once per pixel, persist) --------
    const int w = tid;
    const size_t fbase = (size_t)b * 2 * PLANE + (size_t)h * WW + w;
    const float fx = (float)w + __ldcs(flow + fbase);           // channel 0 = x
    const float fy = (float)h + __ldcs(flow + fbase + PLANE);   // channel 1 = y

    const float x0f = floorf(fx);
    const float y0f = floorf(fy);
    const int   x0  = (int)x0f;
    const int   y0  = (int)y0f;
    const float ax  = fx - x0f;
    const float ay  = fy - y0f;

    float w00 = (1.f - ax) * (1.f - ay);
    float w01 = ax         * (1.f - ay);
    float w10 = (1.f - ax) * ay;
    float w11 = ax         * ay;

    // zero-padding validity (align_corners absolute coords): zero the WEIGHT
    // of any out-of-range corner, gather from clamped index (matches reference).
    const bool vx0 = (x0     >= 0) && (x0     <= WW - 1);
    const bool vx1 = (x0 + 1 >= 0) && (x0 + 1 <= WW - 1);
    const bool vy0 = (y0     >= 0) && (y0     <= HH - 1);
    const bool vy1 = (y0 + 1 >= 0) && (y0 + 1 <= HH - 1);
    if (!(vx0 && vy0)) w00 = 0.f;
    if (!(vx1 && vy0)) w01 = 0.f;
    if (!(vx0 && vy1)) w10 = 0.f;
    if (!(vx1 && vy1)) w11 = 0.f;

    const int cx0 = min(max(x0,     0), WW - 1);
    const int cx1 = min(max(x0 + 1, 0), WW - 1);
    const int cy0 = min(max(y0,     0), HH - 1);
    const int cy1 = min(max(y0 + 1, 0), HH - 1);
    const int o00 = cy0 * WW + cx0;
    const int o01 = cy0 * WW + cx1;
    const int o10 = cy1 * WW + cx0;
    const int o11 = cy1 * WW + cx1;

    // -------- persistent phase-2 state --------
    const int tx = tid & 63;          // pixel-quad index: pixels w0..w0+3
    const int ty = tid >> 6;          // channel-slice owner (16 ch total each)
    const int w0 = tx * 4;
    const int c0 = ty * 8;            // channel offset inside the 32-ch half

    float acc[WIN][4];
    #pragma unroll
    for (int i = 0; i < WIN; ++i) {
        acc[i][0] = 0.f; acc[i][1] = 0.f; acc[i][2] = 0.f; acc[i][3] = 0.f;
    }

    const float* rbase = right + ((size_t)b * CC + (size_t)g * CG) * PLANE;
    const size_t lplane4 = PLANE / 4;
    const float4* lbase = reinterpret_cast<const float4*>(left)
                        + ((size_t)b * CC + (size_t)g * CG) * lplane4
                        + (size_t)h * (WW / 4) + tx;

    // ==================== two 32-channel halves ====================
    #pragma unroll 1
    for (int kh = 0; kh < 2; ++kh) {
        // ---- phase 1: warp right channels [kh*32, kh*32+32) into shared ----
        const float* rb = rbase + (size_t)(kh * CH) * PLANE;
        #pragma unroll 4
        for (int c = 0; c < CH; ++c) {
            const float* p = rb + (size_t)c * PLANE;
            const float v = w00 * __ldg(p + o00)
                          + w01 * __ldg(p + o01)
                          + w10 * __ldg(p + o10)
                          + w11 * __ldg(p + o11);
            float* row = s_rw + c * RWLEN;
            row[w + PAD] = v;
            // edge replication of the WARPED tensor (pad mode="edge")
            if (w == 0) {
                row[0] = v; row[1] = v; row[2] = v; row[3] = v;
            }
            if (w == WW - 1) {
                row[WW + PAD + 0] = v; row[WW + PAD + 1] = v;
                row[WW + PAD + 2] = v; row[WW + PAD + 3] = v;
            }
        }
        __syncthreads();

        // ---- phase 2: 4 px/thread, 8 ch/thread over this half ----
        // left touched exactly once -> streaming loads (__ldcs) keep L2 for
        // right rows. Depth-2 software pipeline: 2 outstanding LDG.128/thread.
        const float4* lp = lbase + (size_t)(kh * CH + c0) * lplane4;
        float4 L0 = __ldcs(lp);
        float4 L1 = __ldcs(lp + lplane4);
        #pragma unroll 1
        for (int c = 0; c < 8; ++c) {
            const float4 L = L0;
            L0 = L1;
            if (c < 6) L1 = __ldcs(lp + (size_t)(c + 2) * lplane4);

            const float* row = s_rw + (c0 + c) * RWLEN + w0;   // 16B aligned
            const float4 q0 = *reinterpret_cast<const float4*>(row);
            const float4 q1 = *reinterpret_cast<const float4*>(row + 4);
            const float4 q2 = *reinterpret_cast<const float4*>(row + 8);
            const float fq[12] = { q0.x, q0.y, q0.z, q0.w,
                                   q1.x, q1.y, q1.z, q1.w,
                                   q2.x, q2.y, q2.z, q2.w };
            const float Lv[4] = { L.x, L.y, L.z, L.w };
            #pragma unroll
            for (int ix = 0; ix < WIN; ++ix) {
                #pragma unroll
                for (int p = 0; p < 4; ++p)
                    acc[ix][p] = fmaf(Lv[p], fq[p + ix], acc[ix][p]);
            }
        }
        __syncthreads();   // phase-2 reads done before next half overwrites smem
    }

    // ========== reduction across the 4 channel-slice owners ==========
    float4* sred = reinterpret_cast<float4*>(s_rw);   // [3][9][64] float4 = 27648 B

    if (ty > 0) {
        const int j = ty - 1;
        #pragma unroll
        for (int ix = 0; ix < WIN; ++ix)
            sred[(j * WIN + ix) * 64 + tx] =
                make_float4(acc[ix][0], acc[ix][1], acc[ix][2], acc[ix][3]);
    }
    __syncthreads();

    if (ty == 0) {
        float* optr = out + ((size_t)b * (GG * WIN) + (size_t)g * WIN) * PLANE
                          + (size_t)h * WW + w0;
        const float inv = 1.0f / (float)CG;
        #pragma unroll
        for (int ix = 0; ix < WIN; ++ix) {
            float vx = acc[ix][0], vy = acc[ix][1], vz = acc[ix][2], vw = acc[ix][3];
            #pragma unroll
            for (int j = 0; j < 3; ++j) {
                const float4 r = sred[(j * WIN + ix) * 64 + tx];
                vx += r.x; vy += r.y; vz += r.z; vw += r.w;
            }
            // output written once, never read -> streaming store keeps L2 for right
            __stcs(reinterpret_cast<float4*>(optr + (size_t)ix * PLANE),
                   make_float4(vx * inv, vy * inv, vz * inv, vw * inv));
        }
    }
}

extern "C" void kernel_launch(void* const* d_in, const int* in_sizes, int n_in,
                              void* d_out, int out_size)
{
    const float* left  = (const float*)d_in[0];
    const float* right = (const float*)d_in[1];
    const float* flow  = (const float*)d_in[2];
    float* out = (float*)d_out;

    const int smem = CH * RWLEN * (int)sizeof(float);   // 33792 B
    cudaFuncSetAttribute(crestereo_corr_kernel,
                         cudaFuncAttributeMaxDynamicSharedMemorySize, smem);

    dim3 grid(BB * GG, HH);
    dim3 block(256);
    crestereo_corr_kernel<<<grid, block, smem>>>(left, right, flow, out);
}

// round 7
// speedup vs baseline: 1.0358x; 1.0358x over previous
#include <cuda_runtime.h>

// Fixed problem shapes
#define BB    4
#define CC    256
#define HH    128
#define WW    256
#define GG    4
#define CG    64             // channels per group
#define CH    32             // channels per smem half
#define WIN   9              // 1x9 window
#define PAD   4
#define RWLEN (WW + 2*PAD)   // 264 floats per padded channel row
#define PLANE (HH*WW)

// 4 blocks/SM (64-reg budget): acc shrunk to 9x2 = 18 regs so both phases
// fit ~55 live regs. 4 x 33.8 KB smem = 135 KB, 32 warps/SM.
// R6 profile: latency-bound (all pipes <35%, issue 15.7%, occ 34.4%) ->
// occupancy is the binding lever, not bandwidth.
__global__ __launch_bounds__(256, 4)
void crestereo_corr_kernel(const float* __restrict__ left,
                           const float* __restrict__ right,
                           const float* __restrict__ flow,
                           float* __restrict__ out)
{
    extern __shared__ float s_rw[];   // [CH][RWLEN] = 32*264 floats = 33792 B

    const int tid = threadIdx.x;      // 0..255
    const int bg  = blockIdx.x;       // 0..15, (b,g) fastest
    const int b   = bg >> 2;
    const int g   = bg & 3;
    const int h   = blockIdx.y;       // 0..127

    // -------- bilinear sampling parameters (once per pixel, persist) --------
    const int w = tid;
    const size_t fbase = (size_t)b * 2 * PLANE + (size_t)h * WW + w;
    const float fx = (float)w + __ldcs(flow + fbase);           // channel 0 = x
    const float fy = (float)h + __ldcs(flow + fbase + PLANE);   // channel 1 = y

    const float x0f = floorf(fx);
    const float y0f = floorf(fy);
    const int   x0  = (int)x0f;
    const int   y0  = (int)y0f;
    const float ax  = fx - x0f;
    const float ay  = fy - y0f;

    float w00 = (1.f - ax) * (1.f - ay);
    float w01 = ax         * (1.f - ay);
    float w10 = (1.f - ax) * ay;
    float w11 = ax         * ay;

    // zero-padding: zero the WEIGHT of out-of-range corners, clamp gather idx
    const bool vx0 = (x0     >= 0) && (x0     <= WW - 1);
    const bool vx1 = (x0 + 1 >= 0) && (x0 + 1 <= WW - 1);
    const bool vy0 = (y0     >= 0) && (y0     <= HH - 1);
    const bool vy1 = (y0 + 1 >= 0) && (y0 + 1 <= HH - 1);
    if (!(vx0 && vy0)) w00 = 0.f;
    if (!(vx1 && vy0)) w01 = 0.f;
    if (!(vx0 && vy1)) w10 = 0.f;
    if (!(vx1 && vy1)) w11 = 0.f;

    const int cx0 = min(max(x0,     0), WW - 1);
    const int cx1 = min(max(x0 + 1, 0), WW - 1);
    const int cy0 = min(max(y0,     0), HH - 1);
    const int cy1 = min(max(y0 + 1, 0), HH - 1);
    const int o00 = cy0 * WW + cx0;
    const int o01 = cy0 * WW + cx1;
    const int o10 = cy1 * WW + cx0;
    const int o11 = cy1 * WW + cx1;

    // -------- persistent phase-2 state: 2 px/thread, 2 channel owners -------
    const int tx = tid & 127;         // pixel-pair index: pixels w0, w0+1
    const int ty = tid >> 7;          // 0..1 channel owner (16 ch per half)
    const int w0 = tx * 2;
    const int c0 = ty * 16;           // channel offset inside the 32-ch half

    float acc[WIN][2];                // 18 regs
    #pragma unroll
    for (int i = 0; i < WIN; ++i) { acc[i][0] = 0.f; acc[i][1] = 0.f; }

    const float* rbase = right + ((size_t)b * CC + (size_t)g * CG) * PLANE;
    const size_t lplane2 = PLANE / 2;
    const float2* lbase = reinterpret_cast<const float2*>(left)
                        + ((size_t)b * CC + (size_t)g * CG) * lplane2
                        + (size_t)h * (WW / 2) + tx;

    // ==================== two 32-channel halves ====================
    #pragma unroll 1
    for (int kh = 0; kh < 2; ++kh) {
        // ---- phase 1: warp right channels [kh*32, kh*32+32) into shared ----
        const float* rb = rbase + (size_t)(kh * CH) * PLANE;
        #pragma unroll 4
        for (int c = 0; c < CH; ++c) {
            const float* p = rb + (size_t)c * PLANE;
            const float v = w00 * __ldg(p + o00)
                          + w01 * __ldg(p + o01)
                          + w10 * __ldg(p + o10)
                          + w11 * __ldg(p + o11);
            float* row = s_rw + c * RWLEN;
            row[w + PAD] = v;
            // edge replication of the WARPED tensor (pad mode="edge")
            if (w == 0) {
                row[0] = v; row[1] = v; row[2] = v; row[3] = v;
            }
            if (w == WW - 1) {
                row[WW + PAD + 0] = v; row[WW + PAD + 1] = v;
                row[WW + PAD + 2] = v; row[WW + PAD + 3] = v;
            }
        }
        __syncthreads();

        // ---- phase 2: 2 px/thread, 16 ch/thread over this half ----
        // left touched once -> streaming loads; depth-2 prefetch (4 regs).
        const float2* lp = lbase + (size_t)(kh * CH + c0) * lplane2;
        float2 L0 = __ldcs(lp);
        float2 L1 = __ldcs(lp + lplane2);
        #pragma unroll 1
        for (int c = 0; c < 16; ++c) {
            const float2 L = L0;
            L0 = L1;
            if (c < 14) L1 = __ldcs(lp + (size_t)(c + 2) * lplane2);

            const float* row = s_rw + (c0 + c) * RWLEN + w0;   // 8B aligned
            const float2 f0 = *reinterpret_cast<const float2*>(row);
            const float2 f1 = *reinterpret_cast<const float2*>(row + 2);
            const float2 f2 = *reinterpret_cast<const float2*>(row + 4);
            const float2 f3 = *reinterpret_cast<const float2*>(row + 6);
            const float2 f4 = *reinterpret_cast<const float2*>(row + 8);
            const float f[10] = { f0.x, f0.y, f1.x, f1.y, f2.x,
                                  f2.y, f3.x, f3.y, f4.x, f4.y };
            #pragma unroll
            for (int ix = 0; ix < WIN; ++ix) {
                acc[ix][0] = fmaf(L.x, f[ix],     acc[ix][0]);
                acc[ix][1] = fmaf(L.y, f[ix + 1], acc[ix][1]);
            }
        }
        __syncthreads();   // phase-2 reads done before next half overwrites smem
    }

    // ========== reduction across the 2 channel owners ==========
    float2* sred = reinterpret_cast<float2*>(s_rw);   // [9][128] float2 = 9216 B

    if (ty == 1) {
        #pragma unroll
        for (int ix = 0; ix < WIN; ++ix)
            sred[ix * 128 + tx] = make_float2(acc[ix][0], acc[ix][1]);
    }
    __syncthreads();

    if (ty == 0) {
        float* optr = out + ((size_t)b * (GG * WIN) + (size_t)g * WIN) * PLANE
                          + (size_t)h * WW + w0;
        const float inv = 1.0f / (float)CG;
        #pragma unroll
        for (int ix = 0; ix < WIN; ++ix) {
            const float2 r = sred[ix * 128 + tx];
            __stcs(reinterpret_cast<float2*>(optr + (size_t)ix * PLANE),
                   make_float2((acc[ix][0] + r.x) * inv,
                               (acc[ix][1] + r.y) * inv));
        }
    }
}

extern "C" void kernel_launch(void* const* d_in, const int* in_sizes, int n_in,
                              void* d_out, int out_size)
{
    const float* left  = (const float*)d_in[0];
    const float* right = (const float*)d_in[1];
    const float* flow  = (const float*)d_in[2];
    float* out = (float*)d_out;

    const int smem = CH * RWLEN * (int)sizeof(float);   // 33792 B
    cudaFuncSetAttribute(crestereo_corr_kernel,
                         cudaFuncAttributeMaxDynamicSharedMemorySize, smem);

    dim3 grid(BB * GG, HH);
    dim3 block(256);
    crestereo_corr_kernel<<<grid, block, smem>>>(left, right, flow, out);
}